// round 1
// baseline (speedup 1.0000x reference)
#include <cuda_runtime.h>
#include <cuda_bf16.h>
#include <cstdint>

// ArcFace loss, fused: theta = (x/|x|) @ (W/|W|)^T ; loss = -mean(num - log(exp(num)+excl))
// B=512, D=512, C=64000.
constexpr int BB = 512;
constexpr int DD = 512;
constexpr int CC = 64000;

constexpr int BM = 256, BN = 128, BK = 16;
constexpr int MT = BB / BM;   // 2
constexpr int NT = CC / BN;   // 500
constexpr int NCH = DD / BK;  // 32
constexpr int AST = 24;       // smem row stride in halfs (48B, conflict-free for ldmatrix)

__device__ float         g_xn[BB * DD];        // normalized x, fp32 (for exact target dot)
__device__ __nv_bfloat16 g_xnb[BB * DD];       // normalized x, bf16 (GEMM A)
__device__ int           g_y[BB];              // decoded labels
__device__ float         g_partial[MT * NT * BM]; // per (mtile,ntile) row partial exp-sums
__device__ double        g_term[BB];           // per-row loss terms

// ---------------------------------------------------------------------------
// k0: decode labels. y may be int64 (reference declares int64) or int32 (JAX
// x64-disabled demotion). Detect: if int64, the int32 view of the first 512
// words is [lo0,hi0,lo1,hi1,...] with all high words == 0 (labels < 64000).
// ---------------------------------------------------------------------------
__global__ void k0_decode_y(const int* __restrict__ yw) {
    __shared__ int oddnz;
    int t = threadIdx.x; // 512 threads
    if (t == 0) oddnz = 0;
    __syncthreads();
    if (t < 256 && yw[2 * t + 1] != 0) atomicOr(&oddnz, 1);
    __syncthreads();
    if (oddnz == 0) {
        g_y[t] = (int)((const long long*)yw)[t];   // int64 layout
    } else {
        g_y[t] = yw[t];                            // int32 layout
    }
}

// ---------------------------------------------------------------------------
// k1: L2-normalize rows of x -> fp32 + bf16 copies. 512 blocks x 128 threads.
// ---------------------------------------------------------------------------
__global__ void k1_norm_x(const float* __restrict__ x) {
    int row = blockIdx.x;
    int t = threadIdx.x; // 128, 4 floats each
    float4 v = ((const float4*)(x + row * DD))[t];
    float ss = v.x * v.x + v.y * v.y + v.z * v.z + v.w * v.w;
    #pragma unroll
    for (int o = 16; o; o >>= 1) ss += __shfl_xor_sync(0xffffffffu, ss, o);
    __shared__ float ws[4];
    if ((t & 31) == 0) ws[t >> 5] = ss;
    __syncthreads();
    float tot = ws[0] + ws[1] + ws[2] + ws[3];
    float sc = 1.0f / fmaxf(sqrtf(tot), 1e-12f);
    float4 o4 = make_float4(v.x * sc, v.y * sc, v.z * sc, v.w * sc);
    ((float4*)(g_xn + row * DD))[t] = o4;
    __nv_bfloat162 p0 = __floats2bfloat162_rn(o4.x, o4.y);
    __nv_bfloat162 p1 = __floats2bfloat162_rn(o4.z, o4.w);
    ((__nv_bfloat162*)(g_xnb + row * DD))[2 * t]     = p0;
    ((__nv_bfloat162*)(g_xnb + row * DD))[2 * t + 1] = p1;
}

// ---------------------------------------------------------------------------
// k2: fused GEMM + column-norm + exp row-sum.
// CTA tile 256M x 128N, K-chunks of 16, double-buffered smem, mma.sync bf16.
// W read raw fp32 from gmem once; converted to bf16 in regs; |W_c|^2
// accumulated alongside; epilogue: theta = acc/|W_c|, e = exp(64*theta),
// masked at the target column, row-summed -> g_partial.
// ---------------------------------------------------------------------------
__device__ __forceinline__ void ldsm4(uint32_t* r, uint32_t a) {
    asm volatile("ldmatrix.sync.aligned.m8n8.x4.shared.b16 {%0,%1,%2,%3}, [%4];"
        : "=r"(r[0]), "=r"(r[1]), "=r"(r[2]), "=r"(r[3]) : "r"(a));
}
__device__ __forceinline__ void mma16816(float* c, const uint32_t* a, uint32_t b0, uint32_t b1) {
    asm volatile("mma.sync.aligned.m16n8k16.row.col.f32.bf16.bf16.f32 "
        "{%0,%1,%2,%3}, {%4,%5,%6,%7}, {%8,%9}, {%0,%1,%2,%3};"
        : "+f"(c[0]), "+f"(c[1]), "+f"(c[2]), "+f"(c[3])
        : "r"(a[0]), "r"(a[1]), "r"(a[2]), "r"(a[3]), "r"(b0), "r"(b1));
}

__global__ __launch_bounds__(256, 1) void k2_gemm(const float* __restrict__ Wm) {
    __shared__ __nv_bfloat16 As[2][BM][AST];
    __shared__ __nv_bfloat16 Bs[2][BN][AST];
    __shared__ int   s_y[BM];
    __shared__ float normpart[BN][4];
    __shared__ float rnorms[BN];
    __shared__ float rowacc[BM][2];

    const int mt = blockIdx.x, nt = blockIdx.y;
    const int m0 = mt * BM, n0 = nt * BN;
    const int t = threadIdx.x, lane = t & 31, wp = t >> 5;
    const int wm = wp >> 1, wn = wp & 1;

    if (t < BM) s_y[t] = g_y[m0 + t];

    const int ar = t >> 1, aq = t & 1;  // A: 2 thr/row, rows ar & ar+128
    const int br = t >> 2, bq = t & 3;  // B: 4 thr/row, rows br & br+64

    float acc[4][8][4];
    #pragma unroll
    for (int i = 0; i < 4; i++)
        #pragma unroll
        for (int j = 0; j < 8; j++)
            #pragma unroll
            for (int k = 0; k < 4; k++) acc[i][j][k] = 0.f;

    float nacc0 = 0.f, nacc1 = 0.f;
    uint4 ra0, ra1; float4 rb0, rb1;

    const __nv_bfloat16* Abase = g_xnb + (m0 + ar) * DD + aq * 8;
    const float*         Bbase = Wm + (n0 + br) * DD + bq * 4;

    auto ldg = [&](int kc) {
        ra0 = *(const uint4*)(Abase + kc * BK);
        ra1 = *(const uint4*)(Abase + 128 * DD + kc * BK);
        rb0 = *(const float4*)(Bbase + kc * BK);
        rb1 = *(const float4*)(Bbase + 64 * DD + kc * BK);
    };
    auto sts = [&](int buf) {
        *(uint4*)&As[buf][ar][aq * 8]       = ra0;
        *(uint4*)&As[buf][ar + 128][aq * 8] = ra1;
        __nv_bfloat162 c0 = __floats2bfloat162_rn(rb0.x, rb0.y);
        __nv_bfloat162 c1 = __floats2bfloat162_rn(rb0.z, rb0.w);
        __nv_bfloat162 c2 = __floats2bfloat162_rn(rb1.x, rb1.y);
        __nv_bfloat162 c3 = __floats2bfloat162_rn(rb1.z, rb1.w);
        *(__nv_bfloat162*)&Bs[buf][br][bq * 4]          = c0;
        *(__nv_bfloat162*)&Bs[buf][br][bq * 4 + 2]      = c1;
        *(__nv_bfloat162*)&Bs[buf][br + 64][bq * 4]     = c2;
        *(__nv_bfloat162*)&Bs[buf][br + 64][bq * 4 + 2] = c3;
        nacc0 += rb0.x * rb0.x + rb0.y * rb0.y + rb0.z * rb0.z + rb0.w * rb0.w;
        nacc1 += rb1.x * rb1.x + rb1.y * rb1.y + rb1.z * rb1.z + rb1.w * rb1.w;
    };

    uint32_t asbase = (uint32_t)__cvta_generic_to_shared(&As[0][0][0]);
    uint32_t bsbase = (uint32_t)__cvta_generic_to_shared(&Bs[0][0][0]);
    uint32_t aoff[4], boff[4];
    #pragma unroll
    for (int mf = 0; mf < 4; mf++)
        aoff[mf] = ((wm * 64 + mf * 16 + (lane & 15)) * AST + (lane >> 4) * 8) * 2;
    #pragma unroll
    for (int nf2 = 0; nf2 < 4; nf2++)
        boff[nf2] = ((wn * 64 + nf2 * 16 + (lane & 15)) * AST + (lane >> 4) * 8) * 2;
    const uint32_t ABUF = BM * AST * 2, BBUF = BN * AST * 2;

    ldg(0); sts(0);
    __syncthreads();

    for (int kc = 0; kc < NCH; kc++) {
        int cur = kc & 1;
        if (kc + 1 < NCH) ldg(kc + 1);
        uint32_t bfrag[4][4];
        #pragma unroll
        for (int nf2 = 0; nf2 < 4; nf2++)
            ldsm4(bfrag[nf2], bsbase + cur * BBUF + boff[nf2]);
        #pragma unroll
        for (int mf = 0; mf < 4; mf++) {
            uint32_t afrag[4];
            ldsm4(afrag, asbase + cur * ABUF + aoff[mf]);
            #pragma unroll
            for (int nf = 0; nf < 8; nf++) {
                int g = nf >> 1, h = nf & 1;
                mma16816(acc[mf][nf], afrag, bfrag[g][h], bfrag[g][2 + h]);
            }
        }
        if (kc + 1 < NCH) sts(cur ^ 1);
        __syncthreads();
    }

    // column norms (deterministic fixed-order reduce)
    normpart[br][bq]      = nacc0;
    normpart[br + 64][bq] = nacc1;
    __syncthreads();
    if (t < BN) {
        float s = normpart[t][0] + normpart[t][1] + normpart[t][2] + normpart[t][3];
        rnorms[t] = 1.0f / fmaxf(sqrtf(s), 1e-12f);
    }
    __syncthreads();

    // epilogue: exp + target mask + row sums
    #pragma unroll
    for (int mf = 0; mf < 4; mf++) {
        #pragma unroll
        for (int h = 0; h < 2; h++) {
            int mlw = wm * 64 + mf * 16 + h * 8 + (lane >> 2);
            int yb = s_y[mlw];
            float rsum = 0.f;
            #pragma unroll
            for (int nf = 0; nf < 8; nf++) {
                #pragma unroll
                for (int j = 0; j < 2; j++) {
                    int nl = wn * 64 + nf * 8 + (lane & 3) * 2 + j;
                    float th = acc[mf][nf][h * 2 + j] * rnorms[nl];
                    float e = expf(64.0f * th);
                    if (n0 + nl == yb) e = 0.f;
                    rsum += e;
                }
            }
            rsum += __shfl_xor_sync(0xffffffffu, rsum, 1);
            rsum += __shfl_xor_sync(0xffffffffu, rsum, 2);
            if ((lane & 3) == 0) rowacc[mlw][wn] = rsum;
        }
    }
    __syncthreads();
    if (t < BM) g_partial[(mt * NT + nt) * BM + t] = rowacc[t][0] + rowacc[t][1];
}

// ---------------------------------------------------------------------------
// k3: per-row finalize. One warp per batch row: sum the 500 tile partials
// (double), recompute the target logit exactly in fp32 (dot + |W_y|), then
// num = 64*cos(acos(clip(tgt)) + 0.5); term = num - log(exp(num) + excl).
// ---------------------------------------------------------------------------
__global__ void k3_final(const float* __restrict__ Wm) {
    int wp = threadIdx.x >> 5, lane = threadIdx.x & 31;
    int b = blockIdx.x * 4 + wp;
    int yb = g_y[b];
    int mt = b >> 8, ml = b & 255;

    double ex = 0.0;
    for (int ntk = lane; ntk < NT; ntk += 32)
        ex += (double)g_partial[(mt * NT + ntk) * BM + ml];

    float dot = 0.f, wss = 0.f;
    const float4* wr = (const float4*)(Wm + (size_t)yb * DD);
    const float4* xr = (const float4*)(g_xn + b * DD);
    #pragma unroll
    for (int i = 0; i < 4; i++) {
        float4 wv = wr[lane + i * 32];
        float4 xv = xr[lane + i * 32];
        dot += wv.x * xv.x + wv.y * xv.y + wv.z * xv.z + wv.w * xv.w;
        wss += wv.x * wv.x + wv.y * wv.y + wv.z * wv.z + wv.w * wv.w;
    }
    #pragma unroll
    for (int o = 16; o; o >>= 1) {
        ex  += __shfl_xor_sync(0xffffffffu, ex, o);
        dot += __shfl_xor_sync(0xffffffffu, dot, o);
        wss += __shfl_xor_sync(0xffffffffu, wss, o);
    }
    if (lane == 0) {
        double tgt = (double)dot / fmax(sqrt((double)wss), 1e-12);
        double tc = fmin(fmax(tgt, -1.0 + 1e-7), 1.0 - 1e-7);
        double num = 64.0 * cos(acos(tc) + 0.5);
        double den = exp(num) + ex;
        g_term[b] = num - log(den);
    }
}

// ---------------------------------------------------------------------------
// k4: final mean. Deterministic tree reduce.
// ---------------------------------------------------------------------------
__global__ void k4_reduce(float* __restrict__ out) {
    __shared__ double sm[BB];
    int t = threadIdx.x;
    sm[t] = g_term[t];
    __syncthreads();
    for (int s = BB / 2; s; s >>= 1) {
        if (t < s) sm[t] += sm[t + s];
        __syncthreads();
    }
    if (t == 0) out[0] = (float)(-sm[0] / (double)BB);
}

extern "C" void kernel_launch(void* const* d_in, const int* in_sizes, int n_in,
                              void* d_out, int out_size) {
    const float* x = (const float*)d_in[0];
    const int*   y = (const int*)d_in[1];
    const float* W = (const float*)d_in[2];

    k0_decode_y<<<1, BB>>>(y);
    k1_norm_x<<<BB, 128>>>(x);
    k2_gemm<<<dim3(MT, NT), 256>>>(W);
    k3_final<<<BB / 4, 128>>>(W);
    k4_reduce<<<1, BB>>>((float*)d_out);
}

// round 3
// speedup vs baseline: 1.0927x; 1.0927x over previous
#include <cuda_runtime.h>
#include <cuda_bf16.h>
#include <cstdint>

// ArcFace loss, fused pipeline. HMMA (mma.sync) GEMM — tcgen05 unavailable
// (harness PTX target is compute_103 base, no 'a' features).
// B=512, D=512, C=64000.
constexpr int BB = 512;
constexpr int DD = 512;
constexpr int CC = 64000;

constexpr int BM = 256, BN = 128, BK = 32;
constexpr int MT = BB / BM;    // 2
constexpr int NT = CC / BN;    // 500
constexpr int NSTG = DD / BK;  // 16 K-stages
constexpr int AROW = 40;       // smem row stride in halfs (80B): ldsm conflict-free
constexpr int A_STG = BM * AROW * 2;  // 20480 B
constexpr int B_STG = BN * AROW * 2;  // 10240 B

// dynamic smem layout
constexpr int A_OFF = 0;                    // 3 stages
constexpr int B_OFF = 3 * A_STG;            // 61440, 3 stages
constexpr int SY_OFF = B_OFF + 3 * B_STG;   // 92160: 256 ints
constexpr int RA_OFF = SY_OFF + 1024;       // 93184: 256x2 floats
constexpr int SMEM_TOTAL = RA_OFF + 2048;   // 95232

__device__ float         g_xn[BB * DD];        // normalized x fp32 (k3 exact dot)
__device__ __nv_bfloat16 g_xnb[BB * DD];       // normalized x bf16 (GEMM A)
__device__ __nv_bfloat16 g_wnb[CC * DD];       // normalized W bf16 (GEMM B)
__device__ int           g_y[BB];
__device__ float         g_partial[MT * NT * BM];
__device__ double        g_term[BB];

// ---------------- PTX helpers ----------------
__device__ __forceinline__ void ldsm4(uint32_t* r, uint32_t a) {
    asm volatile("ldmatrix.sync.aligned.m8n8.x4.shared.b16 {%0,%1,%2,%3}, [%4];"
        : "=r"(r[0]), "=r"(r[1]), "=r"(r[2]), "=r"(r[3]) : "r"(a));
}
__device__ __forceinline__ void mma16816(float* c, const uint32_t* a, uint32_t b0, uint32_t b1) {
    asm volatile("mma.sync.aligned.m16n8k16.row.col.f32.bf16.bf16.f32 "
        "{%0,%1,%2,%3}, {%4,%5,%6,%7}, {%8,%9}, {%0,%1,%2,%3};"
        : "+f"(c[0]), "+f"(c[1]), "+f"(c[2]), "+f"(c[3])
        : "r"(a[0]), "r"(a[1]), "r"(a[2]), "r"(a[3]), "r"(b0), "r"(b1));
}
__device__ __forceinline__ void cpasync16(uint32_t smem, const void* gptr) {
    asm volatile("cp.async.cg.shared.global [%0], [%1], 16;"
        :: "r"(smem), "l"(gptr) : "memory");
}
__device__ __forceinline__ void cpcommit() {
    asm volatile("cp.async.commit_group;" ::: "memory");
}
__device__ __forceinline__ void cpwait1() {
    asm volatile("cp.async.wait_group 1;" ::: "memory");
}

// ---------------------------------------------------------------------------
// k0: decode labels (int64 vs int32 layout sniff; labels < 64000 -> hi words 0)
// ---------------------------------------------------------------------------
__global__ void k0_decode_y(const int* __restrict__ yw) {
    __shared__ int oddnz;
    int t = threadIdx.x;
    if (t == 0) oddnz = 0;
    __syncthreads();
    if (t < 256 && yw[2 * t + 1] != 0) atomicOr(&oddnz, 1);
    __syncthreads();
    if (oddnz == 0) g_y[t] = (int)((const long long*)yw)[t];
    else            g_y[t] = yw[t];
}

// ---------------------------------------------------------------------------
// k1: L2-normalize rows of x -> fp32 + bf16
// ---------------------------------------------------------------------------
__global__ void k1_norm_x(const float* __restrict__ x) {
    int row = blockIdx.x;
    int t = threadIdx.x; // 128
    float4 v = ((const float4*)(x + row * DD))[t];
    float ss = v.x * v.x + v.y * v.y + v.z * v.z + v.w * v.w;
    #pragma unroll
    for (int o = 16; o; o >>= 1) ss += __shfl_xor_sync(0xffffffffu, ss, o);
    __shared__ float ws[4];
    if ((t & 31) == 0) ws[t >> 5] = ss;
    __syncthreads();
    float tot = ws[0] + ws[1] + ws[2] + ws[3];
    float sc = 1.0f / fmaxf(sqrtf(tot), 1e-12f);
    float4 o4 = make_float4(v.x * sc, v.y * sc, v.z * sc, v.w * sc);
    ((float4*)(g_xn + row * DD))[t] = o4;
    __nv_bfloat162 p0 = __floats2bfloat162_rn(o4.x, o4.y);
    __nv_bfloat162 p1 = __floats2bfloat162_rn(o4.z, o4.w);
    ((__nv_bfloat162*)(g_xnb + row * DD))[2 * t]     = p0;
    ((__nv_bfloat162*)(g_xnb + row * DD))[2 * t + 1] = p1;
}

// ---------------------------------------------------------------------------
// k1b: L2-normalize rows of W -> bf16. One warp per row, 8 rows per block.
// ---------------------------------------------------------------------------
__global__ __launch_bounds__(256) void k1b_norm_w(const float* __restrict__ Wm) {
    int wid = threadIdx.x >> 5, lane = threadIdx.x & 31;
    int row = blockIdx.x * 8 + wid;
    const float4* wr = (const float4*)(Wm + (size_t)row * DD);
    float4 v[4];
    float ss = 0.f;
    #pragma unroll
    for (int i = 0; i < 4; i++) {
        v[i] = wr[lane + i * 32];
        ss += v[i].x * v[i].x + v[i].y * v[i].y + v[i].z * v[i].z + v[i].w * v[i].w;
    }
    #pragma unroll
    for (int o = 16; o; o >>= 1) ss += __shfl_xor_sync(0xffffffffu, ss, o);
    float sc = 1.0f / fmaxf(sqrtf(ss), 1e-12f);
    __nv_bfloat162* out = (__nv_bfloat162*)(g_wnb + (size_t)row * DD);
    #pragma unroll
    for (int i = 0; i < 4; i++) {
        __nv_bfloat162 p0 = __floats2bfloat162_rn(v[i].x * sc, v[i].y * sc);
        __nv_bfloat162 p1 = __floats2bfloat162_rn(v[i].z * sc, v[i].w * sc);
        out[(lane + i * 32) * 2]     = p0;
        out[(lane + i * 32) * 2 + 1] = p1;
    }
}

// ---------------------------------------------------------------------------
// k2: HMMA GEMM + fused exp/mask/row-sum epilogue.
// 256Mx128N CTA tile, BK=32, 3-stage cp.async pipeline, bf16 x bf16 (both
// pre-normalized, so theta = acc directly).
// ---------------------------------------------------------------------------
__global__ __launch_bounds__(256, 1) void k2_gemm() {
    extern __shared__ char smem[];
    const uint32_t sb = (uint32_t)__cvta_generic_to_shared(smem);
    const int t = threadIdx.x, lane = t & 31, wp = t >> 5;
    const int wm = wp >> 1, wn = wp & 1;
    const int mt = blockIdx.x, nt = blockIdx.y;
    const int m0 = mt * BM, n0 = nt * BN;

    if (t < BM) ((int*)(smem + SY_OFF))[t] = g_y[m0 + t];

    // cp.async fill: A 256x32 bf16 (4 chunks/thread), B 128x32 bf16 (2/thread)
    auto fillA = [&](int ks, int buf) {
        #pragma unroll
        for (int i = 0; i < 4; i++) {
            int idx = i * 256 + t, r = idx >> 2, c = idx & 3;
            cpasync16(sb + A_OFF + buf * A_STG + (r * AROW + c * 8) * 2,
                      g_xnb + (m0 + r) * DD + ks * BK + c * 8);
        }
    };
    auto fillB = [&](int ks, int buf) {
        #pragma unroll
        for (int i = 0; i < 2; i++) {
            int idx = i * 256 + t, r = idx >> 2, c = idx & 3;
            cpasync16(sb + B_OFF + buf * B_STG + (r * AROW + c * 8) * 2,
                      g_wnb + (size_t)(n0 + r) * DD + ks * BK + c * 8);
        }
    };

    float acc[4][8][4];
    #pragma unroll
    for (int i = 0; i < 4; i++)
        #pragma unroll
        for (int j = 0; j < 8; j++)
            #pragma unroll
            for (int k = 0; k < 4; k++) acc[i][j][k] = 0.f;

    uint32_t aoff[4], boff[4];
    #pragma unroll
    for (int mf = 0; mf < 4; mf++)
        aoff[mf] = sb + A_OFF + ((wm * 64 + mf * 16 + (lane & 15)) * AROW + (lane >> 4) * 8) * 2;
    #pragma unroll
    for (int nf2 = 0; nf2 < 4; nf2++)
        boff[nf2] = sb + B_OFF + ((wn * 64 + nf2 * 16 + (lane & 15)) * AROW + (lane >> 4) * 8) * 2;

    fillA(0, 0); fillB(0, 0); cpcommit();
    fillA(1, 1); fillB(1, 1); cpcommit();

    for (int ks = 0; ks < NSTG; ks++) {
        cpwait1();
        __syncthreads();
        int nx = ks + 2;
        if (nx < NSTG) { fillA(nx, nx % 3); fillB(nx, nx % 3); }
        cpcommit();
        const int buf = ks % 3;
        #pragma unroll
        for (int kc = 0; kc < 2; kc++) {  // two k16 sub-chunks
            uint32_t bfrag[4][4];
            #pragma unroll
            for (int nf2 = 0; nf2 < 4; nf2++)
                ldsm4(bfrag[nf2], boff[nf2] + buf * B_STG + kc * 32);
            #pragma unroll
            for (int mf = 0; mf < 4; mf++) {
                uint32_t afrag[4];
                ldsm4(afrag, aoff[mf] + buf * A_STG + kc * 32);
                #pragma unroll
                for (int nf = 0; nf < 8; nf++) {
                    int g = nf >> 1, h = nf & 1;
                    mma16816(acc[mf][nf], afrag, bfrag[g][h], bfrag[g][2 + h]);
                }
            }
        }
    }
    __syncthreads();

    // epilogue: theta = acc (both operands pre-normalized); exp + mask + rowsum
    const int* sy = (const int*)(smem + SY_OFF);
    float* rowacc = (float*)(smem + RA_OFF);
    #pragma unroll
    for (int mf = 0; mf < 4; mf++) {
        #pragma unroll
        for (int h = 0; h < 2; h++) {
            int mlw = wm * 64 + mf * 16 + h * 8 + (lane >> 2);
            int yrel = sy[mlw] - n0;
            float rsum = 0.f;
            #pragma unroll
            for (int nf = 0; nf < 8; nf++) {
                #pragma unroll
                for (int j = 0; j < 2; j++) {
                    int nl = wn * 64 + nf * 8 + (lane & 3) * 2 + j;
                    float e = __expf(64.0f * acc[mf][nf][h * 2 + j]);
                    rsum += (nl == yrel) ? 0.f : e;
                }
            }
            rsum += __shfl_xor_sync(0xffffffffu, rsum, 1);
            rsum += __shfl_xor_sync(0xffffffffu, rsum, 2);
            if ((lane & 3) == 0) rowacc[mlw * 2 + wn] = rsum;
        }
    }
    __syncthreads();
    if (t < BM)
        g_partial[(mt * NT + nt) * BM + t] = rowacc[t * 2] + rowacc[t * 2 + 1];
}

// ---------------------------------------------------------------------------
// k3: per-row finalize, one block per row (512 blocks x 128 threads).
// Exact target logit from raw fp32 W.
// ---------------------------------------------------------------------------
__global__ void k3_final(const float* __restrict__ Wm) {
    __shared__ double sd[128];
    __shared__ float  sf[128], sg[128];
    int b = blockIdx.x, t = threadIdx.x;
    int yb = g_y[b];
    int mt = b >> 8, ml = b & 255;

    double ex = 0.0;
    for (int nt = t; nt < NT; nt += 128)
        ex += (double)g_partial[(mt * NT + nt) * BM + ml];

    float4 wv = ((const float4*)(Wm + (size_t)yb * DD))[t];
    float4 xv = ((const float4*)(g_xn + b * DD))[t];
    float dot = wv.x * xv.x + wv.y * xv.y + wv.z * xv.z + wv.w * xv.w;
    float wss = wv.x * wv.x + wv.y * wv.y + wv.z * wv.z + wv.w * wv.w;

    sd[t] = ex; sf[t] = dot; sg[t] = wss;
    __syncthreads();
    for (int s = 64; s; s >>= 1) {
        if (t < s) { sd[t] += sd[t + s]; sf[t] += sf[t + s]; sg[t] += sg[t + s]; }
        __syncthreads();
    }
    if (t == 0) {
        double tgt = (double)sf[0] / fmax(sqrt((double)sg[0]), 1e-12);
        double tc = fmin(fmax(tgt, -1.0 + 1e-7), 1.0 - 1e-7);
        double num = 64.0 * cos(acos(tc) + 0.5);
        double den = exp(num) + sd[0];
        g_term[b] = num - log(den);
    }
}

// ---------------------------------------------------------------------------
// k4: mean reduce
// ---------------------------------------------------------------------------
__global__ void k4_reduce(float* __restrict__ out) {
    __shared__ double sm[BB];
    int t = threadIdx.x;
    sm[t] = g_term[t];
    __syncthreads();
    for (int s = BB / 2; s; s >>= 1) {
        if (t < s) sm[t] += sm[t + s];
        __syncthreads();
    }
    if (t == 0) out[0] = (float)(-sm[0] / (double)BB);
}

extern "C" void kernel_launch(void* const* d_in, const int* in_sizes, int n_in,
                              void* d_out, int out_size) {
    const float* x = (const float*)d_in[0];
    const int*   y = (const int*)d_in[1];
    const float* W = (const float*)d_in[2];

    cudaFuncSetAttribute(k2_gemm, cudaFuncAttributeMaxDynamicSharedMemorySize, SMEM_TOTAL);

    k0_decode_y<<<1, BB>>>(y);
    k1_norm_x<<<BB, 128>>>(x);
    k1b_norm_w<<<CC / 8, 256>>>(W);
    k2_gemm<<<dim3(MT, NT), 256, SMEM_TOTAL>>>();
    k3_final<<<BB, 128>>>(W);
    k4_reduce<<<1, BB>>>((float*)d_out);
}